// round 15
// baseline (speedup 1.0000x reference)
#include <cuda_runtime.h>
#include <cstdint>

#define T_STEPS 50
#define BATCH   128
#define NIN     16384
#define NH      256
#define NO      11
#define M_TOT   (T_STEPS * BATCH)     // 6400

#define BM      128
#define BN      128
#define BK      32
#define CHUNKS  (NIN / BK)            // 512
#define KSPLIT  3
#define CPK     171                   // 171+171+170
#define EPS     6e-3f

#define ASW     36                    // smem row stride in floats (32 + 4 pad)

// ---------------------------------------------------------------------------
// Device scratch
// ---------------------------------------------------------------------------
__device__ float g_part[(size_t)KSPLIT * M_TOT * NH];
__device__ float g_cur1[(size_t)M_TOT * NH];
__device__ float g_spk1[(size_t)M_TOT * NH];
__device__ float g_cur2[(size_t)M_TOT * NO];
__device__ int   g_flags[1 + BATCH * NH];

// ---------------------------------------------------------------------------
// helpers
// ---------------------------------------------------------------------------
__device__ __forceinline__ uint32_t tf32r(float f) {
    uint32_t r;
    asm("cvt.rna.tf32.f32 %0, %1;" : "=r"(r) : "f"(f));
    return r;
}

__device__ __forceinline__ void mma_tf32(float* d, const uint32_t* a,
                                         uint32_t b0, uint32_t b1) {
    asm volatile(
        "mma.sync.aligned.m16n8k8.row.col.f32.tf32.tf32.f32 "
        "{%0,%1,%2,%3}, {%4,%5,%6,%7}, {%8,%9}, {%0,%1,%2,%3};"
        : "+f"(d[0]), "+f"(d[1]), "+f"(d[2]), "+f"(d[3])
        : "r"(a[0]), "r"(a[1]), "r"(a[2]), "r"(a[3]), "r"(b0), "r"(b1));
}

// ---------------------------------------------------------------------------
// Kernel 1: partial[ks] = tf32(X) @ tf32(W1)^T  -- single-pass approximate
// Tile 128x128x32, 256 threads (8 warps 2M x 4N, warp tile 64x32).
// R1-style staging: LDG float4 -> regs -> (cvt.rna.tf32) -> STS. grid (2,50,3).
// ---------------------------------------------------------------------------
__global__ __launch_bounds__(256) void gemm_tf32(
    const float* __restrict__ X,
    const float* __restrict__ W1,
    float* __restrict__ part)
{
    __shared__ uint32_t As[BM * ASW];   // [row][k], tf32 bits
    __shared__ uint32_t Bs[BN * ASW];

    const int tid  = threadIdx.x;
    const int wid  = tid >> 5;
    const int lane = tid & 31;
    const int n0 = blockIdx.x * BN;
    const int m0 = blockIdx.y * BM;
    const int c0 = blockIdx.z * CPK;
    const int nch = min(CHUNKS - c0, CPK);
    const int warpM = wid & 1;          // 2 x 64 rows
    const int warpN = wid >> 1;         // 4 x 32 cols
    const int g  = lane >> 2;
    const int tq = lane & 3;

    // loaders: 2 threads per row, 16 floats each (4 float4)
    const int lrow = tid >> 1;
    const int lk   = (tid & 1) * 16;
    const float* xp = X  + (size_t)(m0 + lrow) * NIN + (size_t)c0 * BK + lk;
    const float* wp = W1 + (size_t)(n0 + lrow) * NIN + (size_t)c0 * BK + lk;
    const int sbase = lrow * ASW + lk;

    float acc[4][4][4];
#pragma unroll
    for (int i = 0; i < 4; i++)
#pragma unroll
        for (int j = 0; j < 4; j++)
#pragma unroll
            for (int k = 0; k < 4; k++) acc[i][j][k] = 0.0f;

    float4 xa0 = *reinterpret_cast<const float4*>(xp + 0);
    float4 xa1 = *reinterpret_cast<const float4*>(xp + 4);
    float4 xa2 = *reinterpret_cast<const float4*>(xp + 8);
    float4 xa3 = *reinterpret_cast<const float4*>(xp + 12);
    float4 wa0 = *reinterpret_cast<const float4*>(wp + 0);
    float4 wa1 = *reinterpret_cast<const float4*>(wp + 4);
    float4 wa2 = *reinterpret_cast<const float4*>(wp + 8);
    float4 wa3 = *reinterpret_cast<const float4*>(wp + 12);

    for (int c = 0; c < nch; c++) {
        // stage (with tf32 rounding)
        As[sbase + 0]  = tf32r(xa0.x); As[sbase + 1]  = tf32r(xa0.y);
        As[sbase + 2]  = tf32r(xa0.z); As[sbase + 3]  = tf32r(xa0.w);
        As[sbase + 4]  = tf32r(xa1.x); As[sbase + 5]  = tf32r(xa1.y);
        As[sbase + 6]  = tf32r(xa1.z); As[sbase + 7]  = tf32r(xa1.w);
        As[sbase + 8]  = tf32r(xa2.x); As[sbase + 9]  = tf32r(xa2.y);
        As[sbase + 10] = tf32r(xa2.z); As[sbase + 11] = tf32r(xa2.w);
        As[sbase + 12] = tf32r(xa3.x); As[sbase + 13] = tf32r(xa3.y);
        As[sbase + 14] = tf32r(xa3.z); As[sbase + 15] = tf32r(xa3.w);
        Bs[sbase + 0]  = tf32r(wa0.x); Bs[sbase + 1]  = tf32r(wa0.y);
        Bs[sbase + 2]  = tf32r(wa0.z); Bs[sbase + 3]  = tf32r(wa0.w);
        Bs[sbase + 4]  = tf32r(wa1.x); Bs[sbase + 5]  = tf32r(wa1.y);
        Bs[sbase + 6]  = tf32r(wa1.z); Bs[sbase + 7]  = tf32r(wa1.w);
        Bs[sbase + 8]  = tf32r(wa2.x); Bs[sbase + 9]  = tf32r(wa2.y);
        Bs[sbase + 10] = tf32r(wa2.z); Bs[sbase + 11] = tf32r(wa2.w);
        Bs[sbase + 12] = tf32r(wa3.x); Bs[sbase + 13] = tf32r(wa3.y);
        Bs[sbase + 14] = tf32r(wa3.z); Bs[sbase + 15] = tf32r(wa3.w);
        __syncthreads();

        // prefetch next chunk
        if (c + 1 < nch) {
            const float* xq = xp + (size_t)(c + 1) * BK;
            const float* wq = wp + (size_t)(c + 1) * BK;
            xa0 = *reinterpret_cast<const float4*>(xq + 0);
            xa1 = *reinterpret_cast<const float4*>(xq + 4);
            xa2 = *reinterpret_cast<const float4*>(xq + 8);
            xa3 = *reinterpret_cast<const float4*>(xq + 12);
            wa0 = *reinterpret_cast<const float4*>(wq + 0);
            wa1 = *reinterpret_cast<const float4*>(wq + 4);
            wa2 = *reinterpret_cast<const float4*>(wq + 8);
            wa3 = *reinterpret_cast<const float4*>(wq + 12);
        }

        // compute: 4 k8-steps
#pragma unroll
        for (int ks = 0; ks < 4; ks++) {
            const int kb = ks * 8;
            // B fragments: b0 = B[k=tq][n=colB], b1 = B[k=tq+4][n=colB]
            uint32_t bf[4][2];
#pragma unroll
            for (int nt = 0; nt < 4; nt++) {
                const int colB = warpN * 32 + nt * 8 + g;
                bf[nt][0] = Bs[colB * ASW + kb + tq];
                bf[nt][1] = Bs[colB * ASW + kb + tq + 4];
            }
#pragma unroll
            for (int mt = 0; mt < 4; mt++) {
                const int rowA = warpM * 64 + mt * 16 + g;
                uint32_t af[4];
                af[0] = As[rowA * ASW + kb + tq];
                af[1] = As[(rowA + 8) * ASW + kb + tq];
                af[2] = As[rowA * ASW + kb + tq + 4];
                af[3] = As[(rowA + 8) * ASW + kb + tq + 4];
#pragma unroll
                for (int nt = 0; nt < 4; nt++)
                    mma_tf32(acc[mt][nt], af, bf[nt][0], bf[nt][1]);
            }
        }
        __syncthreads();
    }

    // epilogue: raw partial sums (canonical accumulator map)
    float* po = part + (size_t)blockIdx.z * M_TOT * NH;
#pragma unroll
    for (int nt = 0; nt < 4; nt++) {
        const int col = n0 + warpN * 32 + nt * 8 + tq * 2;
#pragma unroll
        for (int mt = 0; mt < 4; mt++) {
            const int row = m0 + warpM * 64 + mt * 16 + g;
            *reinterpret_cast<float2*>(po + (size_t)row * NH + col) =
                make_float2(acc[mt][nt][0], acc[mt][nt][1]);
            *reinterpret_cast<float2*>(po + (size_t)(row + 8) * NH + col) =
                make_float2(acc[mt][nt][2], acc[mt][nt][3]);
        }
    }
}

// ---------------------------------------------------------------------------
// Kernel 2: reduce 3 partials + bias -> cur1; flag chains whose membrane
// ever comes within EPS of threshold (conservative superset of divergences).
// ---------------------------------------------------------------------------
__global__ __launch_bounds__(256) void reduce_flag(
    const float* __restrict__ part,
    const float* __restrict__ b1,
    float* __restrict__ cur1,
    int* __restrict__ flags)
{
    const int b = blockIdx.x, j = threadIdx.x;
    const float bias = b1[j];
    const size_t P = (size_t)M_TOT * NH;
    const size_t base = (size_t)b * NH + j;
    const size_t ts = (size_t)BATCH * NH;

    float mem = 0.0f;
    bool risky = false;
#pragma unroll 5
    for (int t = 0; t < T_STEPS; t++) {
        const size_t idx = base + (size_t)t * ts;
        const float c = ((part[idx] + part[idx + P]) + part[idx + 2 * P]) + bias;
        cur1[idx] = c;
        mem = 0.9f * mem + c;
        const float d = mem - 1.0f;
        risky |= (fabsf(d) < EPS);
        mem -= (d > 0.0f) ? 1.0f : 0.0f;
    }
    if (risky) {
        const int pos = atomicAdd(&flags[0], 1);
        flags[1 + pos] = (b << 8) | j;
    }
}

// ---------------------------------------------------------------------------
// Kernel 3: bitwise-R1 repair of flagged chains (proven in rounds 12/13).
// One thread per (chain, t); ascending-k fp32 fma chain + single bias add.
// ---------------------------------------------------------------------------
__global__ __launch_bounds__(256) void fix2(
    const float* __restrict__ X,
    const float* __restrict__ W1,
    const float* __restrict__ b1,
    float* __restrict__ cur1,
    const int* __restrict__ flags)
{
    const int total = flags[0] * T_STEPS;
    for (int idx = blockIdx.x * blockDim.x + threadIdx.x; idx < total;
         idx += gridDim.x * blockDim.x) {
        const int ci = idx / T_STEPS;
        const int t  = idx - ci * T_STEPS;
        const int bj = flags[1 + ci];
        const int b = bj >> 8, j = bj & (NH - 1);
        const float* xr = X + ((size_t)t * BATCH + b) * NIN;
        const float* wr = W1 + (size_t)j * NIN;
        float acc = 0.0f;
        for (int k = 0; k < NIN; k += 8) {
            float4 x0 = *reinterpret_cast<const float4*>(xr + k);
            float4 x1 = *reinterpret_cast<const float4*>(xr + k + 4);
            float4 w0 = *reinterpret_cast<const float4*>(wr + k);
            float4 w1 = *reinterpret_cast<const float4*>(wr + k + 4);
            acc = fmaf(x0.x, w0.x, acc);
            acc = fmaf(x0.y, w0.y, acc);
            acc = fmaf(x0.z, w0.z, acc);
            acc = fmaf(x0.w, w0.w, acc);
            acc = fmaf(x1.x, w1.x, acc);
            acc = fmaf(x1.y, w1.y, acc);
            acc = fmaf(x1.z, w1.z, acc);
            acc = fmaf(x1.w, w1.w, acc);
        }
        cur1[((size_t)t * BATCH + b) * NH + j] = acc + b1[j];
    }
}

// ---------------------------------------------------------------------------
// Kernels 4-6: VERBATIM round-14 split scan path (proven bitwise, ~28us)
// ---------------------------------------------------------------------------
__global__ __launch_bounds__(256) void scan1(const float* __restrict__ cur1,
                                             float* __restrict__ spk1) {
    const int b = blockIdx.x, j = threadIdx.x;
    float mem1 = 0.0f;
#pragma unroll 5
    for (int t = 0; t < T_STEPS; t++) {
        const float c1 = cur1[((size_t)t * BATCH + b) * NH + j];
        mem1 = 0.9f * mem1 + c1;
        const float spk = (mem1 - 1.0f > 0.0f) ? 1.0f : 0.0f;
        mem1 -= spk;
        spk1[((size_t)t * BATCH + b) * NH + j] = spk;
    }
}

__global__ __launch_bounds__(256) void layer2k(const float* __restrict__ spk1,
                                               const float* __restrict__ W2,
                                               const float* __restrict__ b2,
                                               float* __restrict__ cur2) {
    const int w8  = threadIdx.x >> 5;
    const int lid = threadIdx.x & 31;
    const int tb  = blockIdx.x * 8 + w8;

    float acc[NO];
#pragma unroll
    for (int o = 0; o < NO; o++) acc[o] = b2[o];

    const float* srow = spk1 + (size_t)tb * NH;

#pragma unroll
    for (int w = 0; w < 8; w++) {
        const float s = srow[w * 32 + lid];
        float p[NO];
#pragma unroll
        for (int o = 0; o < NO; o++) p[o] = s * W2[o * NH + w * 32 + lid];
#pragma unroll
        for (int o = 0; o < NO; o++) {
#pragma unroll
            for (int off = 16; off > 0; off >>= 1)
                p[o] += __shfl_xor_sync(0xFFFFFFFFu, p[o], off);
        }
#pragma unroll
        for (int o = 0; o < NO; o++) {
            const float q0 = __shfl_sync(0xFFFFFFFFu, p[o], 0);
            acc[o] += q0;
        }
    }

    if (lid < NO)
        cur2[(size_t)tb * NO + lid] = acc[lid];
}

__global__ __launch_bounds__(256) void scan2(const float* __restrict__ cur2,
                                             float* __restrict__ out) {
    const int gid = blockIdx.x * 256 + threadIdx.x;
    if (gid >= BATCH * NO) return;
    float mem2 = 0.0f;
#pragma unroll 5
    for (int t = 0; t < T_STEPS; t++) {
        const float c2 = cur2[(size_t)t * BATCH * NO + gid];
        mem2 = 0.9f * mem2 + c2;
        const float spk = (mem2 - 1.0f > 0.0f) ? 1.0f : 0.0f;
        mem2 -= spk;
        out[(size_t)t * BATCH * NO + gid] = spk;
    }
}

// ---------------------------------------------------------------------------
extern "C" void kernel_launch(void* const* d_in, const int* in_sizes, int n_in,
                              void* d_out, int out_size)
{
    const float* x  = (const float*)d_in[0];
    const float* W1 = (const float*)d_in[1];
    const float* b1 = (const float*)d_in[2];
    const float* W2 = (const float*)d_in[3];
    const float* b2 = (const float*)d_in[4];
    float* out = (float*)d_out;

    float *partp, *cur1, *spk1, *cur2;
    int* flagsp;
    cudaGetSymbolAddress((void**)&partp, g_part);
    cudaGetSymbolAddress((void**)&cur1, g_cur1);
    cudaGetSymbolAddress((void**)&spk1, g_spk1);
    cudaGetSymbolAddress((void**)&cur2, g_cur2);
    cudaGetSymbolAddress((void**)&flagsp, g_flags);

    cudaMemsetAsync(flagsp, 0, sizeof(int));
    gemm_tf32<<<dim3(2, 50, KSPLIT), 256>>>(x, W1, partp);
    reduce_flag<<<BATCH, NH>>>(partp, b1, cur1, flagsp);
    fix2<<<592, 256>>>(x, W1, b1, cur1, flagsp);
    scan1<<<BATCH, NH>>>(cur1, spk1);
    layer2k<<<M_TOT / 8, 256>>>(spk1, W2, b2, cur2);
    scan2<<<(BATCH * NO + 255) / 256, 256>>>(cur2, out);
}